// round 7
// baseline (speedup 1.0000x reference)
#include <cuda_runtime.h>
#include <cuda_bf16.h>
#include <math.h>

#define UN 100000
#define NN 150000
#define DD 64
#define EN 3000000
#define BN 8192
#define NEG_SLOPE_F 0.2f
#define NB_SCAN 147   // ceil(NN/1024)

// ---------------- scratch (no allocs allowed -> device globals) ----------------
// Invariant: g_cnt, g_fill, g_ready, g_acc are ZERO at entry of kernel_launch
// (BSS zero-init on first call; finalize_cleanup restores zeros at end of each call).
__device__ int   g_cnt[NN];
__device__ int   g_fill[NN];
__device__ int   g_rowptr[NN + 1];
__device__ int   g_bsums[256];
__device__ int   g_ready;
__device__ int2  g_edge[EN];                 // (col, float-bits val)
__device__ __nv_bfloat16 g_egoh[NN * DD];    // bf16 current embedding (spmm gather source)
__device__ float g_side[NN * DD];            // spmm output
__device__ float g_n1[NN * DD];              // normalized layer-1 embedding
__device__ float g_n2[NN * DD];              // normalized layer-2 embedding
__device__ float g_acc[2];                   // [softplus sum, reg sum]

union U2 { unsigned long long u; float2 f; };

__device__ __forceinline__ void fma2(unsigned long long& d, unsigned long long a, unsigned long long b) {
    asm("fma.rn.f32x2 %0, %1, %2, %0;" : "+l"(d) : "l"(a), "l"(b));
}

// ---------------- fused init (ego copy) + histogram ----------------------------
__global__ void inithist_kernel(const float* __restrict__ ue, const float* __restrict__ ie,
                                const int* __restrict__ rows) {
    int i = blockIdx.x * blockDim.x + threadIdx.x;
    if (i < NN * DD) {
        float v = (i < UN * DD) ? ue[i] : ie[i - UN * DD];
        g_egoh[i] = __float2bfloat16_rn(v);
    }
    if (i < EN) atomicAdd(&g_cnt[rows[i]], 1);   // g_cnt is zero by invariant
}

// ---------------- single-kernel scan: 147 co-resident blocks --------------------
// Each block scans its 1024 slice, publishes its aggregate, waits for all
// aggregates, then locally scans the 147 aggregates to get its block offset.
__global__ void __launch_bounds__(1024) scan_kernel() {
    __shared__ int s[1024];
    int b = blockIdx.x, tid = threadIdx.x;
    int i = b * 1024 + tid;
    int v = (i < NN) ? g_cnt[i] : 0;
    s[tid] = v;
    __syncthreads();
    #pragma unroll
    for (int off = 1; off < 1024; off <<= 1) {
        int t = (tid >= off) ? s[tid - off] : 0;
        __syncthreads();
        s[tid] += t;
        __syncthreads();
    }
    int incl = s[tid];                            // inclusive scan within block
    if (tid == 1023) {
        g_bsums[b] = incl;
        __threadfence();
        atomicAdd(&g_ready, 1);
    }
    if (tid == 0) { while (atomicAdd(&g_ready, 0) < NB_SCAN) {} }
    __syncthreads();
    // read all aggregates via L2 (atomic read bypasses any stale L1)
    int a = 0;
    if (tid < NB_SCAN) a = atomicAdd(&g_bsums[tid], 0);
    __syncthreads();
    if (tid < 256) s[tid] = (tid < NB_SCAN) ? a : 0;
    __syncthreads();
    #pragma unroll
    for (int off = 1; off < 256; off <<= 1) {
        int t = 0;
        if (tid < 256 && tid >= off) t = s[tid - off];
        __syncthreads();
        if (tid < 256) s[tid] += t;
        __syncthreads();
    }
    int blockoff = (b > 0) ? s[b - 1] : 0;        // exclusive offset of this block
    if (i < NN) g_rowptr[i] = incl - v + blockoff;
    if (b == 0 && tid == 0) g_rowptr[NN] = s[NB_SCAN - 1];   // total == EN
}

__global__ void scatter_kernel(const int* __restrict__ rows, const int* __restrict__ cols,
                               const float* __restrict__ vals) {
    int e = blockIdx.x * blockDim.x + threadIdx.x;
    if (e < EN) {
        int r = rows[e];
        int p = g_rowptr[r] + atomicAdd(&g_fill[r], 1);
        g_edge[p] = make_int2(cols[e], __float_as_int(vals[e]));
    }
}

// ---------------- SpMM: warp per row, 16 gathers in flight ----------------------
__global__ void __launch_bounds__(256) spmm_kernel() {
    int w = (blockIdx.x * 256 + threadIdx.x) >> 5;
    int lane = threadIdx.x & 31;
    if (w >= NN) return;
    int s = g_rowptr[w], e = g_rowptr[w + 1];
    float a0 = 0.f, a1 = 0.f;
    int b = s;
    // full batches of 16 edges: cooperative edge load + 16 independent gathers
    for (; b + 16 <= e; b += 16) {
        int2 ed = make_int2(0, 0);
        if (lane < 16) ed = __ldg(&g_edge[b + lane]);
        float2 fs[16]; float vs[16];
        #pragma unroll
        for (int j = 0; j < 16; j++) {
            int   c = __shfl_sync(0xFFFFFFFFu, ed.x, j);
            vs[j]   = __int_as_float(__shfl_sync(0xFFFFFFFFu, ed.y, j));
            __nv_bfloat162 h = __ldg((const __nv_bfloat162*)(g_egoh + c * 64) + lane);
            fs[j] = __bfloat1622float2(h);
        }
        #pragma unroll
        for (int j = 0; j < 16; j++) {
            a0 = fmaf(vs[j], fs[j].x, a0);
            a1 = fmaf(vs[j], fs[j].y, a1);
        }
    }
    // tail (< 16 edges)
    if (b < e) {
        int2 ed = make_int2(0, 0);
        if (lane < 16 && b + lane < e) ed = __ldg(&g_edge[b + lane]);
        int m = e - b;
        for (int j = 0; j < m; j++) {
            int   c = __shfl_sync(0xFFFFFFFFu, ed.x, j);
            float v = __int_as_float(__shfl_sync(0xFFFFFFFFu, ed.y, j));
            __nv_bfloat162 h = __ldg((const __nv_bfloat162*)(g_egoh + c * 64) + lane);
            float2 f = __bfloat1622float2(h);
            a0 = fmaf(v, f.x, a0);
            a1 = fmaf(v, f.y, a1);
        }
    }
    ((float2*)(g_side + w * 64))[lane] = make_float2(a0, a1);
}

// ---------------- fused dense with packed f32x2 FMA (unchanged from R5) ---------
#define W_STRIDE 33
#define OFF_WM  (32 * W_STRIDE * 16)
#define OFF_BG  (2 * 32 * W_STRIDE * 16)
#define OFF_BM  (OFF_BG + 256)
#define OFF_X   (OFF_BM + 256)
#define DSMEM   (OFF_X + 8 * 8 * 32 * 16)

__global__ void __launch_bounds__(256) dense_kernel(
    const float* __restrict__ Wg, const float* __restrict__ bg,
    const float* __restrict__ Wm, const float* __restrict__ bm,
    int layer)
{
    extern __shared__ char sm[];
    float* normOut = (layer == 0) ? g_n1 : g_n2;
    int tid = threadIdx.x;

    {
        float* wgf = (float*)(sm);
        float* wmf = (float*)(sm + OFF_WM);
        for (int i = tid; i < 4096; i += 256) {
            int c = i & 3, kk = (i >> 2) & 31, jj = i >> 7;
            int k = 2 * kk + (c >> 1), col = jj + (c & 1) * 32;
            wgf[(jj * W_STRIDE + kk) * 4 + c] = Wg[k * 64 + col];
            wmf[(jj * W_STRIDE + kk) * 4 + c] = Wm[k * 64 + col];
        }
        if (tid < 32) {
            ((float2*)(sm + OFF_BG))[tid] = make_float2(bg[tid], bg[tid + 32]);
            ((float2*)(sm + OFF_BM))[tid] = make_float2(bm[tid], bm[tid + 32]);
        }
    }
    __syncthreads();

    int warp = tid >> 5, lane = tid & 31;
    const ulonglong2* wgp = (const ulonglong2*)(sm) + lane * W_STRIDE;
    const ulonglong2* wmp = (const ulonglong2*)(sm + OFF_WM) + lane * W_STRIDE;
    unsigned long long bgp = ((const unsigned long long*)(sm + OFF_BG))[lane];
    unsigned long long bmp = ((const unsigned long long*)(sm + OFF_BM))[lane];
    ulonglong2* xr = (ulonglong2*)(sm + OFF_X) + warp * 256;
    float2* xw = (float2*)xr;
    const int l2 = lane + 32;

    const int ngroups = (NN + 7) >> 3;
    for (int grp = blockIdx.x * 8 + warp; grp < ngroups; grp += gridDim.x * 8) {
        int base = grp << 3;
        __syncwarp();
        #pragma unroll
        for (int r = 0; r < 8; r++) {
            int row = base + r;
            float v0 = 0.f, v1 = 0.f;
            if (row < NN) { v0 = g_side[row * 64 + lane]; v1 = g_side[row * 64 + l2]; }
            xw[(r * 32 + (lane >> 1)) * 2 + (lane & 1)] = make_float2(v0, v0);
            xw[(r * 32 + (l2 >> 1)) * 2 + (l2 & 1)]     = make_float2(v1, v1);
        }
        __syncwarp();

        unsigned long long acc[8];
        #pragma unroll
        for (int r = 0; r < 8; r++) acc[r] = bgp;
        #pragma unroll 4
        for (int kk = 0; kk < 32; kk++) {
            ulonglong2 w2 = wgp[kk];
            #pragma unroll
            for (int r = 0; r < 8; r++) {
                ulonglong2 xv = xr[r * 32 + kk];
                fma2(acc[r], xv.x, w2.x);
                fma2(acc[r], xv.y, w2.y);
            }
        }

        __syncwarp();
        #pragma unroll
        for (int r = 0; r < 8; r++) {
            U2 u; u.u = acc[r];
            float gA = u.f.x > 0.f ? u.f.x : NEG_SLOPE_F * u.f.x;
            float gB = u.f.y > 0.f ? u.f.y : NEG_SLOPE_F * u.f.y;
            xw[(r * 32 + (lane >> 1)) * 2 + (lane & 1)] = make_float2(gA, gA);
            xw[(r * 32 + (l2 >> 1)) * 2 + (l2 & 1)]     = make_float2(gB, gB);
        }
        __syncwarp();

        #pragma unroll
        for (int r = 0; r < 8; r++) acc[r] = bmp;
        #pragma unroll 4
        for (int kk = 0; kk < 32; kk++) {
            ulonglong2 w2 = wmp[kk];
            #pragma unroll
            for (int r = 0; r < 8; r++) {
                ulonglong2 xv = xr[r * 32 + kk];
                fma2(acc[r], xv.x, w2.x);
                fma2(acc[r], xv.y, w2.y);
            }
        }

        #pragma unroll
        for (int r = 0; r < 8; r++) {
            U2 u; u.u = acc[r];
            float ss = u.f.x * u.f.x + u.f.y * u.f.y;
            #pragma unroll
            for (int off = 16; off > 0; off >>= 1)
                ss += __shfl_xor_sync(0xFFFFFFFFu, ss, off);
            float inv = 1.0f / fmaxf(sqrtf(ss), 1e-12f);
            int row = base + r;
            if (row < NN) {
                normOut[row * 64 + lane] = u.f.x * inv;
                normOut[row * 64 + l2]   = u.f.y * inv;
                if (layer == 0) {
                    g_egoh[row * 64 + lane] = __float2bfloat16_rn(u.f.x);
                    g_egoh[row * 64 + l2]   = __float2bfloat16_rn(u.f.y);
                }
            }
        }
    }
}

// ---------------- BPR + reg loss: warp per triplet -----------------------------
__global__ void __launch_bounds__(256) loss_kernel(
    const int* __restrict__ user, const int* __restrict__ pos, const int* __restrict__ neg,
    const float* __restrict__ ue, const float* __restrict__ ie)
{
    int w = (blockIdx.x * 256 + threadIdx.x) >> 5;
    int lane = threadIdx.x & 31;
    if (w >= BN) return;
    int uu = user[w], pp = pos[w], nn = neg[w];
    const float* u0 = ue + uu * 64;
    const float* p0 = ie + pp * 64;
    const float* n0 = ie + nn * 64;
    int un = uu * 64, pn = (UN + pp) * 64, nd = (UN + nn) * 64;
    float ps = 0.f, ns = 0.f, rg = 0.f;
    #pragma unroll
    for (int h = 0; h < 2; h++) {
        int l = lane + h * 32;
        float a = u0[l], b = p0[l], c = n0[l];
        ps += a * b; ns += a * c; rg += a * a + b * b + c * c;
        float a1 = g_n1[un + l], b1 = g_n1[pn + l], c1 = g_n1[nd + l];
        ps += a1 * b1; ns += a1 * c1;
        float a2 = g_n2[un + l], b2 = g_n2[pn + l], c2 = g_n2[nd + l];
        ps += a2 * b2; ns += a2 * c2;
    }
    #pragma unroll
    for (int off = 16; off > 0; off >>= 1) {
        ps += __shfl_xor_sync(0xFFFFFFFFu, ps, off);
        ns += __shfl_xor_sync(0xFFFFFFFFu, ns, off);
        rg += __shfl_xor_sync(0xFFFFFFFFu, rg, off);
    }
    if (lane == 0) {
        float x = ns - ps;
        float sp = fmaxf(x, 0.f) + log1pf(expf(-fabsf(x)));
        atomicAdd(&g_acc[0], sp);
        atomicAdd(&g_acc[1], rg);
    }
}

// ---------------- finalize + restore zero-invariant ----------------------------
__global__ void finalize_cleanup_kernel(float* __restrict__ out) {
    int i = blockIdx.x * blockDim.x + threadIdx.x;
    if (i == 0) {
        out[0] = g_acc[0] * (1.0f / (float)BN);
        out[1] = g_acc[1] * (0.5f * 0.0001f / (float)BN);
        g_acc[0] = 0.f; g_acc[1] = 0.f;
        g_ready = 0;
    }
    if (i < NN) { g_cnt[i] = 0; g_fill[i] = 0; }
}

// ---------------- launch -------------------------------------------------------
extern "C" void kernel_launch(void* const* d_in, const int* in_sizes, int n_in,
                              void* d_out, int out_size) {
    const int*   user = (const int*)d_in[0];
    const int*   pos  = (const int*)d_in[1];
    const int*   neg  = (const int*)d_in[2];
    const int*   rows = (const int*)d_in[3];
    const int*   cols = (const int*)d_in[4];
    const float* vals = (const float*)d_in[5];
    const float* ue   = (const float*)d_in[6];
    const float* ie   = (const float*)d_in[7];
    const float* Wg0  = (const float*)d_in[8];
    const float* bg0  = (const float*)d_in[9];
    const float* Wm0  = (const float*)d_in[10];
    const float* bm0  = (const float*)d_in[11];
    const float* Wg1  = (const float*)d_in[12];
    const float* bg1  = (const float*)d_in[13];
    const float* Wm1  = (const float*)d_in[14];
    const float* bm1  = (const float*)d_in[15];
    float* out = (float*)d_out;

    cudaFuncSetAttribute(dense_kernel, cudaFuncAttributeMaxDynamicSharedMemorySize, DSMEM);

    inithist_kernel<<<(NN * DD + 255) / 256, 256>>>(ue, ie, rows);     // idx 0
    scan_kernel<<<NB_SCAN, 1024>>>();                                  // idx 1
    scatter_kernel<<<(EN + 255) / 256, 256>>>(rows, cols, vals);       // idx 2

    spmm_kernel<<<(NN * 32 + 255) / 256, 256>>>();                     // idx 3
    dense_kernel<<<444, 256, DSMEM>>>(Wg0, bg0, Wm0, bm0, 0);          // idx 4
    spmm_kernel<<<(NN * 32 + 255) / 256, 256>>>();                     // idx 5
    dense_kernel<<<444, 256, DSMEM>>>(Wg1, bg1, Wm1, bm1, 1);          // idx 6

    loss_kernel<<<(BN * 32 + 255) / 256, 256>>>(user, pos, neg, ue, ie);   // idx 7
    finalize_cleanup_kernel<<<(NN + 255) / 256, 256>>>(out);           // idx 8
}